// round 16
// baseline (speedup 1.0000x reference)
#include <cuda_runtime.h>
#include <cuda_bf16.h>
#include <cstdint>

// ToroidalSOM squared-distance via mma.sync bf16 split-GEMM, occupancy-first:
//   out[b, n] = ||x_b||^2 + ||w_n||^2 - 2 * dot(x_b, w_n)
// dot = 3 accumulated bf16 HMMA terms (hh + hl + lh), fp32 accumulators.
// Single kernel; x converted per-CTA. Warp tile 16b x 32n (acc = 16 regs),
// __launch_bounds__(256,4) forces regs <= 64 -> 32 warps/SM (2x R14 supply).

#define DIM      64
#define NTOT     16384
#define BATCH    128
#define TILE_N   32
#define THREADS  256

typedef unsigned int u32;

// dynamic smem byte offsets
#define OFF_X_HI   0        // 128 rows x 128B, XOR-16B swizzle
#define OFF_X_LO   16384
#define OFF_W_HI   32768    // 32 rows x 128B
#define OFF_W_LO   36864
#define OFF_WN     40960    // 32 floats
#define OFF_XN     41088    // 128 floats
#define OFF_XNP    41600    // 2 x 128 floats
#define SMEM_TOTAL 42624

__device__ __forceinline__ u32 smem_u32(const void* p) {
    u32 a;
    asm("{ .reg .u64 t; cvta.to.shared.u64 t, %1; cvt.u32.u64 %0, t; }"
        : "=r"(a) : "l"(p));
    return a;
}

__device__ __forceinline__ u32 pack_bf2(__nv_bfloat16 a, __nv_bfloat16 b) {
    __nv_bfloat162 t(a, b);
    return *(u32*)&t;
}

// swizzled byte offset for 4 bf16 elems at (row r, elem col d), d % 4 == 0
__device__ __forceinline__ u32 swz(u32 r, u32 d) {
    return r * 128u + (((d >> 3) ^ (r & 7u)) << 4) + ((d & 4u) << 1);
}

#define LDSM4(r0, r1, r2, r3, addr) \
    asm volatile("ldmatrix.sync.aligned.m8n8.x4.shared.b16 {%0,%1,%2,%3}, [%4];" \
        : "=r"(r0), "=r"(r1), "=r"(r2), "=r"(r3) : "r"(addr))

#define MMA16816(c, a0v, a1v, a2v, a3v, b0v, b1v) \
    asm volatile("mma.sync.aligned.m16n8k16.row.col.f32.bf16.bf16.f32 " \
        "{%0,%1,%2,%3}, {%4,%5,%6,%7}, {%8,%9}, {%0,%1,%2,%3};" \
        : "+f"((c)[0]), "+f"((c)[1]), "+f"((c)[2]), "+f"((c)[3]) \
        : "r"(a0v), "r"(a1v), "r"(a2v), "r"(a3v), "r"(b0v), "r"(b1v))

__global__ __launch_bounds__(THREADS, 4)
void som_mma_kernel(const float* __restrict__ x,
                    const float* __restrict__ w,
                    float* __restrict__ out)
{
    extern __shared__ char smem[];
    const u32 sb  = smem_u32(smem);
    const int tid = threadIdx.x;
    const int wid = tid >> 5;
    const int l   = tid & 31;
    const int nb  = blockIdx.x * TILE_N;

    // ---- stage x (128 x 64): thread -> row tid>>1, dim-half (tid&1)*32 ----
    {
        const int r  = tid >> 1;
        const int c0 = (tid & 1) * 32;
        const float4* xrow = (const float4*)(x + (size_t)r * DIM + c0);
        float xp = 0.f;
        #pragma unroll
        for (int i = 0; i < 8; i++) {
            float4 v = xrow[i];
            const u32 so = swz((u32)r, (u32)(c0 + i * 4));
            __nv_bfloat16 h0 = __float2bfloat16(v.x), h1 = __float2bfloat16(v.y);
            __nv_bfloat16 h2 = __float2bfloat16(v.z), h3 = __float2bfloat16(v.w);
            __nv_bfloat16 l0 = __float2bfloat16(v.x - __bfloat162float(h0));
            __nv_bfloat16 l1 = __float2bfloat16(v.y - __bfloat162float(h1));
            __nv_bfloat16 l2 = __float2bfloat16(v.z - __bfloat162float(h2));
            __nv_bfloat16 l3 = __float2bfloat16(v.w - __bfloat162float(h3));
            *(uint2*)(smem + OFF_X_HI + so) = make_uint2(pack_bf2(h0,h1), pack_bf2(h2,h3));
            *(uint2*)(smem + OFF_X_LO + so) = make_uint2(pack_bf2(l0,l1), pack_bf2(l2,l3));
            xp = fmaf(v.x, v.x, fmaf(v.y, v.y, fmaf(v.z, v.z, fmaf(v.w, v.w, xp))));
        }
        ((float*)(smem + OFF_XNP))[(tid & 1) * 128 + r] = xp;
    }

    // ---- stage w tile (32 x 64): thread -> row tid>>3, 8 dims at (tid&7)*8 ----
    {
        const int r  = tid >> 3;
        const int c0 = (tid & 7) * 8;
        const float4* wrow = (const float4*)(w + (size_t)(nb + r) * DIM + c0);
        float wp = 0.f;
        #pragma unroll
        for (int i = 0; i < 2; i++) {
            float4 v = wrow[i];
            const u32 so = swz((u32)r, (u32)(c0 + i * 4));
            __nv_bfloat16 h0 = __float2bfloat16(v.x), h1 = __float2bfloat16(v.y);
            __nv_bfloat16 h2 = __float2bfloat16(v.z), h3 = __float2bfloat16(v.w);
            __nv_bfloat16 l0 = __float2bfloat16(v.x - __bfloat162float(h0));
            __nv_bfloat16 l1 = __float2bfloat16(v.y - __bfloat162float(h1));
            __nv_bfloat16 l2 = __float2bfloat16(v.z - __bfloat162float(h2));
            __nv_bfloat16 l3 = __float2bfloat16(v.w - __bfloat162float(h3));
            *(uint2*)(smem + OFF_W_HI + so) = make_uint2(pack_bf2(h0,h1), pack_bf2(h2,h3));
            *(uint2*)(smem + OFF_W_LO + so) = make_uint2(pack_bf2(l0,l1), pack_bf2(l2,l3));
            wp = fmaf(v.x, v.x, fmaf(v.y, v.y, fmaf(v.z, v.z, fmaf(v.w, v.w, wp))));
        }
        // reduce over the 8 lanes sharing row r (consecutive lanes)
        wp += __shfl_xor_sync(0xFFFFFFFFu, wp, 1);
        wp += __shfl_xor_sync(0xFFFFFFFFu, wp, 2);
        wp += __shfl_xor_sync(0xFFFFFFFFu, wp, 4);
        if ((tid & 7) == 0) ((float*)(smem + OFF_WN))[r] = wp;
    }
    __syncthreads();

    // ---- x norms reduce ----
    if (tid < 128) {
        const float* p = (const float*)(smem + OFF_XNP);
        ((float*)(smem + OFF_XN))[tid] = p[tid] + p[128 + tid];
    }
    __syncthreads();

    // ---- main loop: warp tile 16 (batch) x 32 (neuron) ----
    const int m0  = wid * 16;                         // 8 warps cover 128 batches
    const u32 rA  = (u32)(m0 + (l & 15));
    const u32 cA  = (u32)((l >> 4) & 1);
    const u32 rB0 = (u32)((l & 7) + ((l >> 4) & 1) * 8);
    const u32 rB1 = rB0 + 16;
    const u32 cB  = (u32)((l >> 3) & 1);

    float acc[4][4];
    #pragma unroll
    for (int nt = 0; nt < 4; nt++)
        #pragma unroll
        for (int r = 0; r < 4; r++) acc[nt][r] = 0.f;

    const u32 xhi = sb + OFF_X_HI, xlo = sb + OFF_X_LO;
    const u32 whi = sb + OFF_W_HI, wlo = sb + OFF_W_LO;

    #pragma unroll
    for (int ks = 0; ks < 4; ks++) {
        const u32 kc = (u32)(ks * 2);
        const u32 aoff  = rA  * 128u + (((kc + cA) ^ (rA  & 7u)) << 4);
        const u32 boff0 = rB0 * 128u + (((kc + cB) ^ (rB0 & 7u)) << 4);
        const u32 boff1 = rB1 * 128u + (((kc + cB) ^ (rB1 & 7u)) << 4);

        u32 ah[4], al[4], bh0[4], bh1[4], bl0[4], bl1[4];
        LDSM4(ah[0], ah[1], ah[2], ah[3], xhi + aoff);
        LDSM4(al[0], al[1], al[2], al[3], xlo + aoff);
        LDSM4(bh0[0], bh0[1], bh0[2], bh0[3], whi + boff0);
        LDSM4(bh1[0], bh1[1], bh1[2], bh1[3], whi + boff1);
        LDSM4(bl0[0], bl0[1], bl0[2], bl0[3], wlo + boff0);
        LDSM4(bl1[0], bl1[1], bl1[2], bl1[3], wlo + boff1);

        // hh
        MMA16816(acc[0], ah[0], ah[1], ah[2], ah[3], bh0[0], bh0[1]);
        MMA16816(acc[1], ah[0], ah[1], ah[2], ah[3], bh0[2], bh0[3]);
        MMA16816(acc[2], ah[0], ah[1], ah[2], ah[3], bh1[0], bh1[1]);
        MMA16816(acc[3], ah[0], ah[1], ah[2], ah[3], bh1[2], bh1[3]);
        // hl
        MMA16816(acc[0], ah[0], ah[1], ah[2], ah[3], bl0[0], bl0[1]);
        MMA16816(acc[1], ah[0], ah[1], ah[2], ah[3], bl0[2], bl0[3]);
        MMA16816(acc[2], ah[0], ah[1], ah[2], ah[3], bl1[0], bl1[1]);
        MMA16816(acc[3], ah[0], ah[1], ah[2], ah[3], bl1[2], bl1[3]);
        // lh
        MMA16816(acc[0], al[0], al[1], al[2], al[3], bh0[0], bh0[1]);
        MMA16816(acc[1], al[0], al[1], al[2], al[3], bh0[2], bh0[3]);
        MMA16816(acc[2], al[0], al[1], al[2], al[3], bh1[0], bh1[1]);
        MMA16816(acc[3], al[0], al[1], al[2], al[3], bh1[2], bh1[3]);
    }

    // ---- epilogue: dist = xn + wn - 2*dot; float2 stores ----
    const float* xn = (const float*)(smem + OFF_XN);
    const float* wn = (const float*)(smem + OFF_WN);
    const int row = m0 + (l >> 2);
    const int t2  = (l & 3) * 2;
    const float xn0 = xn[row];
    const float xn1 = xn[row + 8];

    #pragma unroll
    for (int nt = 0; nt < 4; nt++) {
        const int nl = nt * 8 + t2;
        const float w0 = wn[nl];
        const float w1 = wn[nl + 1];
        const size_t o = (size_t)row * NTOT + nb + nl;

        float2 r0, r1;
        r0.x = fmaf(-2.f, acc[nt][0], xn0 + w0);
        r0.y = fmaf(-2.f, acc[nt][1], xn0 + w1);
        r1.x = fmaf(-2.f, acc[nt][2], xn1 + w0);
        r1.y = fmaf(-2.f, acc[nt][3], xn1 + w1);

        *(float2*)&out[o]                    = r0;
        *(float2*)&out[o + (size_t)8 * NTOT] = r1;
    }
}

extern "C" void kernel_launch(void* const* d_in, const int* in_sizes, int n_in,
                              void* d_out, int out_size)
{
    const float* x = (const float*)d_in[0];   // (128, 64)
    const float* w = (const float*)d_in[1];   // (16384, 64)
    float* out = (float*)d_out;               // (128, 16384)

    cudaFuncSetAttribute(som_mma_kernel,
                         cudaFuncAttributeMaxDynamicSharedMemorySize, SMEM_TOTAL);
    som_mma_kernel<<<NTOT / TILE_N, THREADS, SMEM_TOTAL>>>(x, w, out);
}

// round 17
// speedup vs baseline: 1.3499x; 1.3499x over previous
#include <cuda_runtime.h>
#include <cuda_bf16.h>
#include <cstdint>

// ToroidalSOM squared-distance via mma.sync bf16 split-GEMM (R14 structure,
// deduplicated fragment loads + cp.async staging):
//   out[b, n] = ||x_b||^2 + ||w_n||^2 - 2 * dot(x_b, w_n)
// dot = 3 accumulated bf16 HMMA terms (hh + hl + lh), fp32 accumulators.
//
// Kernel A (prep): x (128x64) -> swizzled bf16 hi/lo tile images + x-norms.
// Kernel B: 512 CTAs (TILE_N=32), 128 threads, warp tile 32b x 32n.
//   Per k-step: 8 independent LDSM.x4 (A-hi/lo x2 rows, B-hi/lo x2 rows)
//   then 24 HMMA -> 32 LDSM + 96 HMMA per warp (was 48 + 96 in R14).

#define DIM      64
#define NTOT     16384
#define BATCH    128
#define TILE_N   32
#define THREADS  128

typedef unsigned int u32;

// x scratch: exact smem tile images (128 rows x 128B, XOR-16B swizzle)
__device__ __align__(16) unsigned char x_hi_g[BATCH * 128];
__device__ __align__(16) unsigned char x_lo_g[BATCH * 128];
__device__ float xn_g[BATCH];

// dynamic smem offsets (kernel B)
#define OFF_X_HI   0
#define OFF_X_LO   16384
#define OFF_W_HI   32768   // 32 rows x 128B
#define OFF_W_LO   36864
#define OFF_WN     40960   // 32 floats
#define OFF_XN     41088   // 128 floats
#define SMEM_TOTAL 41600

__device__ __forceinline__ u32 smem_u32(const void* p) {
    u32 a;
    asm("{ .reg .u64 t; cvta.to.shared.u64 t, %1; cvt.u32.u64 %0, t; }"
        : "=r"(a) : "l"(p));
    return a;
}

__device__ __forceinline__ u32 pack_bf2(__nv_bfloat16 a, __nv_bfloat16 b) {
    __nv_bfloat162 t(a, b);
    return *(u32*)&t;
}

// swizzled byte offset for 4 bf16 elems at (row r, elem col d), d % 4 == 0
__device__ __forceinline__ u32 swz(u32 r, u32 d) {
    return r * 128u + (((d >> 3) ^ (r & 7u)) << 4) + ((d & 4u) << 1);
}

#define LDSM4(r0, r1, r2, r3, addr) \
    asm volatile("ldmatrix.sync.aligned.m8n8.x4.shared.b16 {%0,%1,%2,%3}, [%4];" \
        : "=r"(r0), "=r"(r1), "=r"(r2), "=r"(r3) : "r"(addr))

#define MMA16816(c, a, b0v, b1v) \
    asm volatile("mma.sync.aligned.m16n8k16.row.col.f32.bf16.bf16.f32 " \
        "{%0,%1,%2,%3}, {%4,%5,%6,%7}, {%8,%9}, {%0,%1,%2,%3};" \
        : "+f"((c)[0]), "+f"((c)[1]), "+f"((c)[2]), "+f"((c)[3]) \
        : "r"((a)[0]), "r"((a)[1]), "r"((a)[2]), "r"((a)[3]), \
          "r"(b0v), "r"(b1v))

#define CP_ASYNC16(saddr, gptr) \
    asm volatile("cp.async.cg.shared.global [%0], [%1], 16;" \
        :: "r"(saddr), "l"(gptr) : "memory")

// ---- Kernel A: prep x (grid 8 x 128 threads) ----
__global__ __launch_bounds__(128)
void prep_x_kernel(const float* __restrict__ x)
{
    const int t = threadIdx.x;
    const int r = blockIdx.x * 16 + (t >> 3);   // batch row
    const int c = (t & 7) * 8;                  // dim base (8 dims)

    const float4* xr = (const float4*)(x + (size_t)r * DIM + c);
    float xp = 0.f;
    #pragma unroll
    for (int i = 0; i < 2; i++) {
        float4 v = xr[i];
        const u32 so = swz((u32)r, (u32)(c + i * 4));
        __nv_bfloat16 h0 = __float2bfloat16(v.x), h1 = __float2bfloat16(v.y);
        __nv_bfloat16 h2 = __float2bfloat16(v.z), h3 = __float2bfloat16(v.w);
        __nv_bfloat16 l0 = __float2bfloat16(v.x - __bfloat162float(h0));
        __nv_bfloat16 l1 = __float2bfloat16(v.y - __bfloat162float(h1));
        __nv_bfloat16 l2 = __float2bfloat16(v.z - __bfloat162float(h2));
        __nv_bfloat16 l3 = __float2bfloat16(v.w - __bfloat162float(h3));
        *(uint2*)(x_hi_g + so) = make_uint2(pack_bf2(h0, h1), pack_bf2(h2, h3));
        *(uint2*)(x_lo_g + so) = make_uint2(pack_bf2(l0, l1), pack_bf2(l2, l3));
        xp = fmaf(v.x, v.x, fmaf(v.y, v.y, fmaf(v.z, v.z, fmaf(v.w, v.w, xp))));
    }
    xp += __shfl_xor_sync(0xFFFFFFFFu, xp, 1);
    xp += __shfl_xor_sync(0xFFFFFFFFu, xp, 2);
    xp += __shfl_xor_sync(0xFFFFFFFFu, xp, 4);
    if ((t & 7) == 0) xn_g[r] = xp;
}

// ---- Kernel B: main GEMM + epilogue ----
__global__ __launch_bounds__(THREADS)
void som_mma_kernel(const float* __restrict__ w,
                    float* __restrict__ out)
{
    extern __shared__ char smem[];
    const u32 sb  = smem_u32(smem);
    const int tid = threadIdx.x;
    const int wid = tid >> 5;
    const int l   = tid & 31;
    const int nb  = blockIdx.x * TILE_N;

    // -- x tiles: cp.async 32KB (streams while we convert w below) --
    {
        unsigned long long ghi, glo;
        asm("cvta.to.global.u64 %0, %1;" : "=l"(ghi) : "l"((const void*)x_hi_g));
        asm("cvta.to.global.u64 %0, %1;" : "=l"(glo) : "l"((const void*)x_lo_g));
        const u32 dhi = sb + OFF_X_HI + (u32)tid * 16u;
        const u32 dlo = sb + OFF_X_LO + (u32)tid * 16u;
        #pragma unroll
        for (int i = 0; i < 8; i++) {
            CP_ASYNC16(dhi + (u32)i * 2048u, ghi + (u32)tid * 16u + (u32)i * 2048u);
            CP_ASYNC16(dlo + (u32)i * 2048u, glo + (u32)tid * 16u + (u32)i * 2048u);
        }
        asm volatile("cp.async.commit_group;" ::: "memory");
    }

    // -- x norms to smem (L2-resident) --
    ((float*)(smem + OFF_XN))[tid] = xn_g[tid];

    // -- stage w tile (32 neurons x 64 dims): 4 threads/row, 16 dims each --
    {
        const int r  = tid >> 2;
        const int c0 = (tid & 3) * 16;
        const float4* wrow = (const float4*)(w + (size_t)(nb + r) * DIM + c0);
        float wp = 0.f;
        #pragma unroll
        for (int i = 0; i < 4; i++) {
            float4 v = wrow[i];
            const u32 so = swz((u32)r, (u32)(c0 + i * 4));
            __nv_bfloat16 h0 = __float2bfloat16(v.x), h1 = __float2bfloat16(v.y);
            __nv_bfloat16 h2 = __float2bfloat16(v.z), h3 = __float2bfloat16(v.w);
            __nv_bfloat16 l0 = __float2bfloat16(v.x - __bfloat162float(h0));
            __nv_bfloat16 l1 = __float2bfloat16(v.y - __bfloat162float(h1));
            __nv_bfloat16 l2 = __float2bfloat16(v.z - __bfloat162float(h2));
            __nv_bfloat16 l3 = __float2bfloat16(v.w - __bfloat162float(h3));
            *(uint2*)(smem + OFF_W_HI + so) = make_uint2(pack_bf2(h0,h1), pack_bf2(h2,h3));
            *(uint2*)(smem + OFF_W_LO + so) = make_uint2(pack_bf2(l0,l1), pack_bf2(l2,l3));
            wp = fmaf(v.x, v.x, fmaf(v.y, v.y, fmaf(v.z, v.z, fmaf(v.w, v.w, wp))));
        }
        wp += __shfl_xor_sync(0xFFFFFFFFu, wp, 1);
        wp += __shfl_xor_sync(0xFFFFFFFFu, wp, 2);
        if ((tid & 3) == 0) ((float*)(smem + OFF_WN))[r] = wp;
    }

    asm volatile("cp.async.wait_group 0;" ::: "memory");
    __syncthreads();

    // -- main loop: warp tile 32 (batch) x 32 (neuron) --
    const int m0  = wid * 32;
    const u32 rA0 = (u32)(m0 + (l & 7) + ((l >> 3) & 1) * 8);
    const u32 rA1 = rA0 + 16;
    const u32 cA  = (u32)((l >> 4) & 1);
    const u32 rB0 = (u32)((l & 7) + ((l >> 4) & 1) * 8);
    const u32 rB1 = rB0 + 16;
    const u32 cB  = (u32)((l >> 3) & 1);

    float acc[2][4][4];
    #pragma unroll
    for (int mt = 0; mt < 2; mt++)
        #pragma unroll
        for (int nt = 0; nt < 4; nt++)
            #pragma unroll
            for (int r = 0; r < 4; r++) acc[mt][nt][r] = 0.f;

    const u32 xhi = sb + OFF_X_HI, xlo = sb + OFF_X_LO;
    const u32 whi = sb + OFF_W_HI, wlo = sb + OFF_W_LO;

    #pragma unroll
    for (int ks = 0; ks < 4; ks++) {
        const u32 kc = (u32)(ks * 2);
        const u32 aoff0 = rA0 * 128u + (((kc + cA) ^ (rA0 & 7u)) << 4);
        const u32 aoff1 = rA1 * 128u + (((kc + cA) ^ (rA1 & 7u)) << 4);
        const u32 boff0 = rB0 * 128u + (((kc + cB) ^ (rB0 & 7u)) << 4);
        const u32 boff1 = rB1 * 128u + (((kc + cB) ^ (rB1 & 7u)) << 4);

        // 8 independent fragment loads (all buffers, both row blocks)
        u32 ah0[4], ah1[4], al0[4], al1[4];
        u32 bh0[4], bh1[4], bl0[4], bl1[4];
        LDSM4(ah0[0], ah0[1], ah0[2], ah0[3], xhi + aoff0);
        LDSM4(ah1[0], ah1[1], ah1[2], ah1[3], xhi + aoff1);
        LDSM4(al0[0], al0[1], al0[2], al0[3], xlo + aoff0);
        LDSM4(al1[0], al1[1], al1[2], al1[3], xlo + aoff1);
        LDSM4(bh0[0], bh0[1], bh0[2], bh0[3], whi + boff0);
        LDSM4(bh1[0], bh1[1], bh1[2], bh1[3], whi + boff1);
        LDSM4(bl0[0], bl0[1], bl0[2], bl0[3], wlo + boff0);
        LDSM4(bl1[0], bl1[1], bl1[2], bl1[3], wlo + boff1);

        // hh
        MMA16816(acc[0][0], ah0, bh0[0], bh0[1]);
        MMA16816(acc[1][0], ah1, bh0[0], bh0[1]);
        MMA16816(acc[0][1], ah0, bh0[2], bh0[3]);
        MMA16816(acc[1][1], ah1, bh0[2], bh0[3]);
        MMA16816(acc[0][2], ah0, bh1[0], bh1[1]);
        MMA16816(acc[1][2], ah1, bh1[0], bh1[1]);
        MMA16816(acc[0][3], ah0, bh1[2], bh1[3]);
        MMA16816(acc[1][3], ah1, bh1[2], bh1[3]);
        // hl
        MMA16816(acc[0][0], ah0, bl0[0], bl0[1]);
        MMA16816(acc[1][0], ah1, bl0[0], bl0[1]);
        MMA16816(acc[0][1], ah0, bl0[2], bl0[3]);
        MMA16816(acc[1][1], ah1, bl0[2], bl0[3]);
        MMA16816(acc[0][2], ah0, bl1[0], bl1[1]);
        MMA16816(acc[1][2], ah1, bl1[0], bl1[1]);
        MMA16816(acc[0][3], ah0, bl1[2], bl1[3]);
        MMA16816(acc[1][3], ah1, bl1[2], bl1[3]);
        // lh
        MMA16816(acc[0][0], al0, bh0[0], bh0[1]);
        MMA16816(acc[1][0], al1, bh0[0], bh0[1]);
        MMA16816(acc[0][1], al0, bh0[2], bh0[3]);
        MMA16816(acc[1][1], al1, bh0[2], bh0[3]);
        MMA16816(acc[0][2], al0, bh1[0], bh1[1]);
        MMA16816(acc[1][2], al1, bh1[0], bh1[1]);
        MMA16816(acc[0][3], al0, bh1[2], bh1[3]);
        MMA16816(acc[1][3], al1, bh1[2], bh1[3]);
    }

    // -- epilogue: dist = xn + wn - 2*dot; float2 stores --
    const float* xn = (const float*)(smem + OFF_XN);
    const float* wn = (const float*)(smem + OFF_WN);

    #pragma unroll
    for (int mt = 0; mt < 2; mt++) {
        const int mg = m0 + mt * 16 + (l >> 2);
        const float xn0 = xn[mg];
        const float xn1 = xn[mg + 8];
        #pragma unroll
        for (int nt = 0; nt < 4; nt++) {
            const int nl = nt * 8 + (l & 3) * 2;
            const float w0 = wn[nl];
            const float w1 = wn[nl + 1];
            const size_t o = (size_t)mg * NTOT + nb + nl;

            float2 r0, r1;
            r0.x = fmaf(-2.f, acc[mt][nt][0], xn0 + w0);
            r0.y = fmaf(-2.f, acc[mt][nt][1], xn0 + w1);
            r1.x = fmaf(-2.f, acc[mt][nt][2], xn1 + w0);
            r1.y = fmaf(-2.f, acc[mt][nt][3], xn1 + w1);

            *(float2*)&out[o]                    = r0;
            *(float2*)&out[o + (size_t)8 * NTOT] = r1;
        }
    }
}

extern "C" void kernel_launch(void* const* d_in, const int* in_sizes, int n_in,
                              void* d_out, int out_size)
{
    const float* x = (const float*)d_in[0];   // (128, 64)
    const float* w = (const float*)d_in[1];   // (16384, 64)
    float* out = (float*)d_out;               // (128, 16384)

    prep_x_kernel<<<8, 128>>>(x);
    cudaFuncSetAttribute(som_mma_kernel,
                         cudaFuncAttributeMaxDynamicSharedMemorySize, SMEM_TOTAL);
    som_mma_kernel<<<NTOT / TILE_N, THREADS, SMEM_TOTAL>>>(w, out);
}